// round 4
// baseline (speedup 1.0000x reference)
#include <cuda_runtime.h>
#include <math.h>

// Problem constants
#define NN    50000
#define EE    800000
#define DIN   64
#define HIDD  128
#define DOUTC 64
#define BB    2

// ---------------- scratch (static device globals; no allocation) ----------------
__device__ float g_h [BB * NN * 128];   // projected features for current layer
__device__ float g_el[BB * NN * 2];     // per-node attention left  (max 2 heads)
__device__ float g_er[BB * NN * 2];     // per-node attention right
__device__ float g_y1[BB * NN * 128];   // layer1 output
__device__ float g_y2[BB * NN * 128];   // layer2 output
__device__ float g_w [BB * EE * 2];     // per-edge softmax numerators, CSR order
__device__ int   g_rowptr[NN + 1];      // CSR by dst
__device__ int   g_cursor[NN];          // degree / scatter cursor
__device__ int   g_csrc[EE];            // src per CSR slot
__device__ int   g_cdst[EE];            // dst per CSR slot (quasi-sorted)

// ---------------- packed fp32x2 helpers ----------------
__device__ __forceinline__ void fma2(unsigned long long& d,
                                     unsigned long long a,
                                     unsigned long long b) {
    asm("fma.rn.f32x2 %0, %1, %2, %0;" : "+l"(d) : "l"(a), "l"(b));
}
__device__ __forceinline__ float2 up2(unsigned long long v) {
    float2 r;
    asm("mov.b64 {%0, %1}, %2;" : "=f"(r.x), "=f"(r.y) : "l"(v));
    return r;
}

// ---------------- CSR build ----------------
__global__ void zero_deg_kernel() {
    int i = blockIdx.x * blockDim.x + threadIdx.x;
    if (i < NN) g_cursor[i] = 0;
}

__global__ void hist_kernel(const int* __restrict__ dst) {
    int e = blockIdx.x * blockDim.x + threadIdx.x;
    if (e < EE) atomicAdd(&g_cursor[dst[e]], 1);
}

__global__ void scan_kernel() {
    __shared__ int ss[1024];
    const int t  = threadIdx.x;
    const int CH = (NN + 1023) / 1024;
    const int b  = t * CH;
    const int e  = min(b + CH, NN);
    int s = 0;
    for (int i = b; i < e; i++) s += g_cursor[i];
    ss[t] = s;
    __syncthreads();
    for (int off = 1; off < 1024; off <<= 1) {
        int v = (t >= off) ? ss[t - off] : 0;
        __syncthreads();
        ss[t] += v;
        __syncthreads();
    }
    int run = (t == 0) ? 0 : ss[t - 1];
    for (int i = b; i < e; i++) {
        int d = g_cursor[i];
        g_rowptr[i] = run;
        g_cursor[i] = run;
        run += d;
    }
    if (t == 1023) g_rowptr[NN] = ss[1023];
}

__global__ void scatter_kernel(const int* __restrict__ src, const int* __restrict__ dst) {
    int e = blockIdx.x * blockDim.x + threadIdx.x;
    if (e < EE) {
        int d = dst[e];
        int p = atomicAdd(&g_cursor[d], 1);
        g_csrc[p] = src[e];
        g_cdst[p] = d;
    }
}

// ---------------- tiled GEMM (f32x2) + attention coefficients ----------------
template <int K, int HD, int H>
__global__ __launch_bounds__(256) void gemm_att_kernel(
    const float* __restrict__ xbase, size_t xstride,
    const float* __restrict__ W,
    const float* __restrict__ al, const float* __restrict__ ar,
    float* __restrict__ hbase, float* __restrict__ elbase, float* __restrict__ erbase)
{
    constexpr int TM  = 64;
    constexpr int KC  = 16;
    constexpr int CG  = HD / 4;
    constexpr int RT  = TM / (256 / CG);
    constexpr int NP  = RT / 2;
    constexpr int D   = HD / H;
    constexpr int LPHW = (CG / H) < 32 ? (CG / H) : 32;
    constexpr int WITER = (KC * HD / 4 + 255) / 256;

    __shared__ __align__(16) float xs [KC][TM + 4];
    __shared__ __align__(16) float ws2[KC][2 * HD];

    const float* x    = xbase  + (size_t)blockIdx.y * xstride;
    float*       hout = hbase  + (size_t)blockIdx.y * NN * HD;
    float*       el   = elbase + (size_t)blockIdx.y * NN * H;
    float*       er   = erbase + (size_t)blockIdx.y * NN * H;

    const int tid  = threadIdx.x;
    const int lane = tid & 31;
    const int cg   = tid % CG;
    const int rg   = tid / CG;
    const int c0   = cg * 4;
    const int rb   = rg * RT;
    const int row0 = blockIdx.x * TM;

    unsigned long long acc[NP][4];
    #pragma unroll
    for (int p = 0; p < NP; p++)
        #pragma unroll
        for (int c = 0; c < 4; c++) acc[p][c] = 0ull;

    const int lr = tid >> 2;
    const int lj = tid & 3;
    const int lrow = min(row0 + lr, NN - 1);
    const float4* xrow = reinterpret_cast<const float4*>(x + (size_t)lrow * K);

    for (int kc = 0; kc < K; kc += KC) {
        float4 xv = xrow[(kc >> 2) + lj];
        xs[lj * 4 + 0][lr] = xv.x;
        xs[lj * 4 + 1][lr] = xv.y;
        xs[lj * 4 + 2][lr] = xv.z;
        xs[lj * 4 + 3][lr] = xv.w;
        #pragma unroll
        for (int it = 0; it < WITER; it++) {
            int fi = tid + it * 256;
            if (fi < KC * HD / 4) {
                int k  = fi / (HD / 4);
                int cq = fi % (HD / 4);
                float4 wv = *reinterpret_cast<const float4*>(W + (size_t)(kc + k) * HD + cq * 4);
                *reinterpret_cast<float4*>(&ws2[k][cq * 8])     = make_float4(wv.x, wv.x, wv.y, wv.y);
                *reinterpret_cast<float4*>(&ws2[k][cq * 8 + 4]) = make_float4(wv.z, wv.z, wv.w, wv.w);
            }
        }
        __syncthreads();

        #pragma unroll
        for (int k = 0; k < KC; k++) {
            ulonglong2 wa = *reinterpret_cast<const ulonglong2*>(&ws2[k][2 * c0]);
            ulonglong2 wb = *reinterpret_cast<const ulonglong2*>(&ws2[k][2 * c0 + 4]);
            ulonglong2 xa = *reinterpret_cast<const ulonglong2*>(&xs[k][rb]);
            fma2(acc[0][0], xa.x, wa.x);
            fma2(acc[0][1], xa.x, wa.y);
            fma2(acc[0][2], xa.x, wb.x);
            fma2(acc[0][3], xa.x, wb.y);
            fma2(acc[1][0], xa.y, wa.x);
            fma2(acc[1][1], xa.y, wa.y);
            fma2(acc[1][2], xa.y, wb.x);
            fma2(acc[1][3], xa.y, wb.y);
            if constexpr (NP == 4) {
                ulonglong2 xb = *reinterpret_cast<const ulonglong2*>(&xs[k][rb + 4]);
                fma2(acc[2][0], xb.x, wa.x);
                fma2(acc[2][1], xb.x, wa.y);
                fma2(acc[2][2], xb.x, wb.x);
                fma2(acc[2][3], xb.x, wb.y);
                fma2(acc[3][0], xb.y, wa.x);
                fma2(acc[3][1], xb.y, wa.y);
                fma2(acc[3][2], xb.y, wb.x);
                fma2(acc[3][3], xb.y, wb.y);
            }
        }
        __syncthreads();
    }

    float vals[RT][4];
    #pragma unroll
    for (int p = 0; p < NP; p++)
        #pragma unroll
        for (int c = 0; c < 4; c++) {
            float2 f = up2(acc[p][c]);
            vals[p * 2 + 0][c] = f.x;
            vals[p * 2 + 1][c] = f.y;
        }

    #pragma unroll
    for (int i = 0; i < RT; i++) {
        int row = row0 + rb + i;
        if (row < NN)
            *reinterpret_cast<float4*>(hout + (size_t)row * HD + c0) =
                make_float4(vals[i][0], vals[i][1], vals[i][2], vals[i][3]);
    }

    float al4[4], ar4[4];
    #pragma unroll
    for (int c = 0; c < 4; c++) { al4[c] = al[c0 + c]; ar4[c] = ar[c0 + c]; }
    const int hh = c0 / D;

    #pragma unroll
    for (int i = 0; i < RT; i++) {
        float pel = 0.f, per_ = 0.f;
        #pragma unroll
        for (int c = 0; c < 4; c++) {
            pel  = fmaf(vals[i][c], al4[c], pel);
            per_ = fmaf(vals[i][c], ar4[c], per_);
        }
        #pragma unroll
        for (int off = LPHW >> 1; off > 0; off >>= 1) {
            pel  += __shfl_xor_sync(0xffffffffu, pel,  off);
            per_ += __shfl_xor_sync(0xffffffffu, per_, off);
        }
        int row = row0 + rb + i;
        if ((lane & (LPHW - 1)) == 0 && row < NN) {
            el[row * H + hh] = pel;
            er[row * H + hh] = per_;
        }
    }
}

// ---------------- per-edge softmax numerators (CSR order, both batches) ------
// One thread per CSR slot. csrc/cdst reads coalesced, el gather random 4B,
// er gather quasi-sequential (slots sorted by dst), w writes coalesced.
template <int H>
__global__ __launch_bounds__(256) void weight_kernel(
    const float* __restrict__ elbase, const float* __restrict__ erbase)
{
    int p = blockIdx.x * blockDim.x + threadIdx.x;
    if (p >= EE) return;
    const int s = g_csrc[p];
    const int d = g_cdst[p];
    const float* el0 = elbase;
    const float* el1 = elbase + NN * H;
    const float* er0 = erbase;
    const float* er1 = erbase + NN * H;
    float* w0 = g_w;
    float* w1 = g_w + (size_t)EE * H;
    #pragma unroll
    for (int h = 0; h < H; h++) {
        float v0 = el0[s * H + h] + er0[d * H + h];
        float v1 = el1[s * H + h] + er1[d * H + h];
        v0 = (v0 > 0.f) ? v0 : 0.2f * v0;
        v1 = (v1 > 0.f) ? v1 : 0.2f * v1;
        w0[p * H + h] = __expf(v0);
        w1[p * H + h] = __expf(v1);
    }
}

// ---------------- aggregation: precomputed weights, 4-edge unroll ------------
// One warp per destination node, both batches. Inner loop: coalesced w/csrc
// loads, then 8 independent float4 h-gathers in flight, then FMAs.
template <int HD, int H, bool RELU>
__global__ __launch_bounds__(256, 2) void aggregate3_kernel(
    const float* __restrict__ hbase, const float* __restrict__ bias,
    float* __restrict__ outbase, size_t outstride)
{
    constexpr int VW = HD / 32;
    constexpr int D  = HD / H;

    const float* h0 = hbase;
    const float* h1 = hbase + (size_t)NN * HD;
    const float* w0 = g_w;
    const float* w1 = g_w + (size_t)EE * H;
    float*       o0 = outbase;
    float*       o1 = outbase + outstride;

    const int gw   = (blockIdx.x * blockDim.x + threadIdx.x) >> 5;
    const int lane = threadIdx.x & 31;
    if (gw >= NN) return;

    const int s0 = g_rowptr[gw];
    const int s1 = g_rowptr[gw + 1];
    const int c0 = lane * VW;
    const int hl = c0 / D;

    float acc0[VW], acc1[VW];
    #pragma unroll
    for (int j = 0; j < VW; j++) { acc0[j] = 0.f; acc1[j] = 0.f; }
    float sum0 = 0.f, sum1 = 0.f;

    int p = s0;
    for (; p + 4 <= s1; p += 4) {
        const int iA = g_csrc[p];
        const int iB = g_csrc[p + 1];
        const int iC = g_csrc[p + 2];
        const int iD = g_csrc[p + 3];
        const float wa0 = w0[(p + 0) * H + hl];
        const float wb0 = w0[(p + 1) * H + hl];
        const float wc0 = w0[(p + 2) * H + hl];
        const float wd0 = w0[(p + 3) * H + hl];
        const float wa1 = w1[(p + 0) * H + hl];
        const float wb1 = w1[(p + 1) * H + hl];
        const float wc1 = w1[(p + 2) * H + hl];
        const float wd1 = w1[(p + 3) * H + hl];

        if constexpr (VW == 4) {
            float4 A0 = *reinterpret_cast<const float4*>(h0 + (size_t)iA * HD + c0);
            float4 B0 = *reinterpret_cast<const float4*>(h0 + (size_t)iB * HD + c0);
            float4 C0 = *reinterpret_cast<const float4*>(h0 + (size_t)iC * HD + c0);
            float4 D0 = *reinterpret_cast<const float4*>(h0 + (size_t)iD * HD + c0);
            float4 A1 = *reinterpret_cast<const float4*>(h1 + (size_t)iA * HD + c0);
            float4 B1 = *reinterpret_cast<const float4*>(h1 + (size_t)iB * HD + c0);
            float4 C1 = *reinterpret_cast<const float4*>(h1 + (size_t)iC * HD + c0);
            float4 D1 = *reinterpret_cast<const float4*>(h1 + (size_t)iD * HD + c0);
            sum0 += (wa0 + wb0) + (wc0 + wd0);
            sum1 += (wa1 + wb1) + (wc1 + wd1);
            acc0[0] = fmaf(wa0, A0.x, acc0[0]); acc0[0] = fmaf(wb0, B0.x, acc0[0]);
            acc0[0] = fmaf(wc0, C0.x, acc0[0]); acc0[0] = fmaf(wd0, D0.x, acc0[0]);
            acc0[1] = fmaf(wa0, A0.y, acc0[1]); acc0[1] = fmaf(wb0, B0.y, acc0[1]);
            acc0[1] = fmaf(wc0, C0.y, acc0[1]); acc0[1] = fmaf(wd0, D0.y, acc0[1]);
            acc0[2] = fmaf(wa0, A0.z, acc0[2]); acc0[2] = fmaf(wb0, B0.z, acc0[2]);
            acc0[2] = fmaf(wc0, C0.z, acc0[2]); acc0[2] = fmaf(wd0, D0.z, acc0[2]);
            acc0[3] = fmaf(wa0, A0.w, acc0[3]); acc0[3] = fmaf(wb0, B0.w, acc0[3]);
            acc0[3] = fmaf(wc0, C0.w, acc0[3]); acc0[3] = fmaf(wd0, D0.w, acc0[3]);
            acc1[0] = fmaf(wa1, A1.x, acc1[0]); acc1[0] = fmaf(wb1, B1.x, acc1[0]);
            acc1[0] = fmaf(wc1, C1.x, acc1[0]); acc1[0] = fmaf(wd1, D1.x, acc1[0]);
            acc1[1] = fmaf(wa1, A1.y, acc1[1]); acc1[1] = fmaf(wb1, B1.y, acc1[1]);
            acc1[1] = fmaf(wc1, C1.y, acc1[1]); acc1[1] = fmaf(wd1, D1.y, acc1[1]);
            acc1[2] = fmaf(wa1, A1.z, acc1[2]); acc1[2] = fmaf(wb1, B1.z, acc1[2]);
            acc1[2] = fmaf(wc1, C1.z, acc1[2]); acc1[2] = fmaf(wd1, D1.z, acc1[2]);
            acc1[3] = fmaf(wa1, A1.w, acc1[3]); acc1[3] = fmaf(wb1, B1.w, acc1[3]);
            acc1[3] = fmaf(wc1, C1.w, acc1[3]); acc1[3] = fmaf(wd1, D1.w, acc1[3]);
        } else {
            float2 A0 = *reinterpret_cast<const float2*>(h0 + (size_t)iA * HD + c0);
            float2 B0 = *reinterpret_cast<const float2*>(h0 + (size_t)iB * HD + c0);
            float2 C0 = *reinterpret_cast<const float2*>(h0 + (size_t)iC * HD + c0);
            float2 D0 = *reinterpret_cast<const float2*>(h0 + (size_t)iD * HD + c0);
            float2 A1 = *reinterpret_cast<const float2*>(h1 + (size_t)iA * HD + c0);
            float2 B1 = *reinterpret_cast<const float2*>(h1 + (size_t)iB * HD + c0);
            float2 C1 = *reinterpret_cast<const float2*>(h1 + (size_t)iC * HD + c0);
            float2 D1 = *reinterpret_cast<const float2*>(h1 + (size_t)iD * HD + c0);
            sum0 += (wa0 + wb0) + (wc0 + wd0);
            sum1 += (wa1 + wb1) + (wc1 + wd1);
            acc0[0] = fmaf(wa0, A0.x, acc0[0]); acc0[0] = fmaf(wb0, B0.x, acc0[0]);
            acc0[0] = fmaf(wc0, C0.x, acc0[0]); acc0[0] = fmaf(wd0, D0.x, acc0[0]);
            acc0[1] = fmaf(wa0, A0.y, acc0[1]); acc0[1] = fmaf(wb0, B0.y, acc0[1]);
            acc0[1] = fmaf(wc0, C0.y, acc0[1]); acc0[1] = fmaf(wd0, D0.y, acc0[1]);
            acc1[0] = fmaf(wa1, A1.x, acc1[0]); acc1[0] = fmaf(wb1, B1.x, acc1[0]);
            acc1[0] = fmaf(wc1, C1.x, acc1[0]); acc1[0] = fmaf(wd1, D1.x, acc1[0]);
            acc1[1] = fmaf(wa1, A1.y, acc1[1]); acc1[1] = fmaf(wb1, B1.y, acc1[1]);
            acc1[1] = fmaf(wc1, C1.y, acc1[1]); acc1[1] = fmaf(wd1, D1.y, acc1[1]);
        }
    }
    for (; p < s1; p++) {
        const int iA = g_csrc[p];
        const float wa0 = w0[p * H + hl];
        const float wa1 = w1[p * H + hl];
        sum0 += wa0;
        sum1 += wa1;
        if constexpr (VW == 4) {
            float4 A0 = *reinterpret_cast<const float4*>(h0 + (size_t)iA * HD + c0);
            float4 A1 = *reinterpret_cast<const float4*>(h1 + (size_t)iA * HD + c0);
            acc0[0] = fmaf(wa0, A0.x, acc0[0]);
            acc0[1] = fmaf(wa0, A0.y, acc0[1]);
            acc0[2] = fmaf(wa0, A0.z, acc0[2]);
            acc0[3] = fmaf(wa0, A0.w, acc0[3]);
            acc1[0] = fmaf(wa1, A1.x, acc1[0]);
            acc1[1] = fmaf(wa1, A1.y, acc1[1]);
            acc1[2] = fmaf(wa1, A1.z, acc1[2]);
            acc1[3] = fmaf(wa1, A1.w, acc1[3]);
        } else {
            float2 A0 = *reinterpret_cast<const float2*>(h0 + (size_t)iA * HD + c0);
            float2 A1 = *reinterpret_cast<const float2*>(h1 + (size_t)iA * HD + c0);
            acc0[0] = fmaf(wa0, A0.x, acc0[0]);
            acc0[1] = fmaf(wa0, A0.y, acc0[1]);
            acc1[0] = fmaf(wa1, A1.x, acc1[0]);
            acc1[1] = fmaf(wa1, A1.y, acc1[1]);
        }
    }

    float bv[VW];
    #pragma unroll
    for (int j = 0; j < VW; j++) bv[j] = bias[c0 + j];

    float out0[VW], out1[VW];
    if (s1 > s0) {
        const float i0 = 1.f / sum0;
        const float i1 = 1.f / sum1;
        #pragma unroll
        for (int j = 0; j < VW; j++) {
            out0[j] = fmaf(acc0[j], i0, bv[j]);
            out1[j] = fmaf(acc1[j], i1, bv[j]);
        }
    } else {
        #pragma unroll
        for (int j = 0; j < VW; j++) { out0[j] = bv[j]; out1[j] = bv[j]; }
    }
    if (RELU) {
        #pragma unroll
        for (int j = 0; j < VW; j++) {
            out0[j] = fmaxf(out0[j], 0.f);
            out1[j] = fmaxf(out1[j], 0.f);
        }
    }

    if constexpr (VW == 4) {
        *reinterpret_cast<float4*>(o0 + (size_t)gw * HD + c0) =
            make_float4(out0[0], out0[1], out0[2], out0[3]);
        *reinterpret_cast<float4*>(o1 + (size_t)gw * HD + c0) =
            make_float4(out1[0], out1[1], out1[2], out1[3]);
    } else {
        *reinterpret_cast<float2*>(o0 + (size_t)gw * HD + c0) =
            make_float2(out0[0], out0[1]);
        *reinterpret_cast<float2*>(o1 + (size_t)gw * HD + c0) =
            make_float2(out1[0], out1[1]);
    }
}

// ---------------- launcher ----------------
extern "C" void kernel_launch(void* const* d_in, const int* in_sizes, int n_in,
                              void* d_out, int out_size)
{
    const float* input = (const float*)d_in[0];
    const int*   src   = (const int*)  d_in[1];
    const int*   dst   = (const int*)  d_in[2];
    const float* W1    = (const float*)d_in[3];
    const float* al1   = (const float*)d_in[4];
    const float* ar1   = (const float*)d_in[5];
    const float* b1    = (const float*)d_in[6];
    const float* W2    = (const float*)d_in[7];
    const float* al2   = (const float*)d_in[8];
    const float* ar2   = (const float*)d_in[9];
    const float* b2    = (const float*)d_in[10];
    const float* W3    = (const float*)d_in[11];
    const float* al3   = (const float*)d_in[12];
    const float* ar3   = (const float*)d_in[13];
    const float* b3    = (const float*)d_in[14];
    float* out = (float*)d_out;

    void *ph, *pel, *per, *py1, *py2;
    cudaGetSymbolAddress(&ph,  g_h);
    cudaGetSymbolAddress(&pel, g_el);
    cudaGetSymbolAddress(&per, g_er);
    cudaGetSymbolAddress(&py1, g_y1);
    cudaGetSymbolAddress(&py2, g_y2);
    float* hbuf = (float*)ph;
    float* elb  = (float*)pel;
    float* erb  = (float*)per;
    float* y1   = (float*)py1;
    float* y2   = (float*)py2;

    // CSR build (edges identical across batches/layers -> build once per launch)
    zero_deg_kernel<<<(NN + 255) / 256, 256>>>();
    hist_kernel<<<(EE + 255) / 256, 256>>>(dst);
    scan_kernel<<<1, 1024>>>();
    scatter_kernel<<<(EE + 255) / 256, 256>>>(src, dst);

    dim3 ggrid((NN + 63) / 64, BB);
    const int agrid = (NN * 32 + 255) / 256;
    const int wgrid = (EE + 255) / 256;

    // Layer 1: GATConv(64 -> 2 heads x 64)
    gemm_att_kernel<64, 128, 2><<<ggrid, 256>>>(input, (size_t)NN * DIN, W1, al1, ar1, hbuf, elb, erb);
    weight_kernel<2><<<wgrid, 256>>>(elb, erb);
    aggregate3_kernel<128, 2, false><<<agrid, 256>>>(hbuf, b1, y1, (size_t)NN * 128);

    // Layer 2: GATConv(128 -> 128, 1 head), ReLU
    gemm_att_kernel<128, 128, 1><<<ggrid, 256>>>(y1, (size_t)NN * 128, W2, al2, ar2, hbuf, elb, erb);
    weight_kernel<1><<<wgrid, 256>>>(elb, erb);
    aggregate3_kernel<128, 1, true><<<agrid, 256>>>(hbuf, b2, y2, (size_t)NN * 128);

    // Layer 3: GATConv(128 -> 64, 1 head)
    gemm_att_kernel<128, 64, 1><<<ggrid, 256>>>(y2, (size_t)NN * 128, W3, al3, ar3, hbuf, elb, erb);
    weight_kernel<1><<<wgrid, 256>>>(elb, erb);
    aggregate3_kernel<64, 1, false><<<agrid, 256>>>(hbuf, b3, out, (size_t)NN * DOUTC);
}